// round 13
// baseline (speedup 1.0000x reference)
#include <cuda_runtime.h>
#include <cuda_fp16.h>
#include <math.h>
#include <stdint.h>

// Problem dims
#define Dm    1024
#define Cm    2048
#define MLPm  4096
#define Hh    16
#define HDh   64
#define Bb    8
#define Nn    512
#define Ss    2048
#define INNER (Hh*HDh)   // 1024
#define EPSf  1e-6f

// ---------------- scratch (static device allocations) ---------------------------
__device__ __align__(16) float  d_mods  [3 * Bb * 3 * Dm];
__device__ __align__(16) __half d_normed[Bb * Nn * Dm];
__device__ __align__(16) __half d_qkv   [Bb * Nn * 3 * INNER];
__device__ __align__(16) __half d_kv    [(size_t)Bb * Ss * 2 * INNER];
__device__ __align__(16) __half d_attno [Bb * Nn * INNER];
__device__ __align__(16) float  d_x1    [Bb * Nn * Dm];
__device__ __align__(16) float  d_x2    [Bb * Nn * Dm];
__device__ __align__(16) __half d_hbuf  [Bb * Nn * MLPm];
__device__ __align__(16) __half d_ctx   [(size_t)Bb * Ss * Cm];
__device__ __align__(16) __half d_wrnd  [22 * 1024 * 1024];

// weight offsets (elements); adjacency is load-bearing for fused GEMMs:
// [SAQ|SAK|SAV] 3072x1024, [CAK|CAV] 2048x2048, FFGU interleaved 8192x1024
#define W_SAQ  (0)
#define W_SAO  (3*1024*1024)
#define W_CAQ  (4*1024*1024)
#define W_CAK  (5*1024*1024)
#define W_CAO  (9*1024*1024)
#define W_FFGU (10*1024*1024)
#define W_FFD  (18*1024*1024)

// ---------------- helpers ---------------------------------------------------------
__device__ __forceinline__ void mma_f16(float* c, const uint32_t* a, const uint32_t* b) {
    asm volatile(
        "mma.sync.aligned.m16n8k16.row.col.f32.f16.f16.f32 "
        "{%0,%1,%2,%3}, {%4,%5,%6,%7}, {%8,%9}, {%0,%1,%2,%3};\n"
        : "+f"(c[0]), "+f"(c[1]), "+f"(c[2]), "+f"(c[3])
        : "r"(a[0]), "r"(a[1]), "r"(a[2]), "r"(a[3]), "r"(b[0]), "r"(b[1]));
}

__device__ __forceinline__ void cpasync16(uint32_t saddr, const void* gptr) {
    asm volatile("cp.async.cg.shared.global [%0], [%1], 16;\n" :: "r"(saddr), "l"(gptr));
}
__device__ __forceinline__ void cp_commit() { asm volatile("cp.async.commit_group;\n"); }
template<int n> __device__ __forceinline__ void cp_wait() {
    asm volatile("cp.async.wait_group %0;\n" :: "n"(n));
}
__device__ __forceinline__ uint32_t cvta_smem(const void* p) {
    uint32_t a;
    asm("{ .reg .u64 t; cvta.to.shared.u64 t, %1; cvt.u32.u64 %0, t; }" : "=r"(a) : "l"(p));
    return a;
}
__device__ __forceinline__ void ldsm_x4(uint32_t& r0, uint32_t& r1, uint32_t& r2, uint32_t& r3,
                                        uint32_t addr) {
    asm volatile("ldmatrix.sync.aligned.m8n8.x4.shared.b16 {%0,%1,%2,%3}, [%4];"
                 : "=r"(r0), "=r"(r1), "=r"(r2), "=r"(r3) : "r"(addr));
}
__device__ __forceinline__ void ldsm_x4_trans(uint32_t& r0, uint32_t& r1, uint32_t& r2, uint32_t& r3,
                                              uint32_t addr) {
    asm volatile("ldmatrix.sync.aligned.m8n8.x4.trans.shared.b16 {%0,%1,%2,%3}, [%4];"
                 : "=r"(r0), "=r"(r1), "=r"(r2), "=r"(r3) : "r"(addr));
}
__device__ __forceinline__ uint32_t pack_h2(float a, float b) {
    __half2 h = __floats2half2_rn(a, b);
    return *(uint32_t*)&h;
}

// ---------------- fp16 NT GEMM: C(M,N) = A(M,K) @ B(N,K)^T ----------------------
// 128x128 CTA tile, 128 threads (4 warps 2x2, warp tile 64x64), BK=64,
// row pad 72 halves, 3-stage cp.async ring with TRUE 2-deep prefetch, 2 CTAs/SM.
// EPI==1: add resid + gate[(row/rows_per_b)*gate_ld+col]*acc (float out)
// OH: 0 = float out, 1 = half out, 2 = silu-pair: h[row][col/2] = silu(even)*odd
template<int EPI,int OH>
__global__ void __launch_bounds__(128, 2)
gemm_f16(const __half* __restrict__ A, const __half* __restrict__ Bg, void* __restrict__ Cv,
         int K, int lda, int ldb, int ldc,
         const float* __restrict__ resid, const float* __restrict__ gate,
         int gate_ld, int rows_per_b)
{
    constexpr int BM = 128, BN = 128, BK = 64, LDH = 72, ST = 3;

    extern __shared__ __half hsm[];
    __half* As = hsm;
    __half* Bs = hsm + ST * BM * LDH;

    const int tid = threadIdx.x, wid = tid >> 5, lane = tid & 31;
    const int g = lane >> 2, c4 = lane & 3;
    const int q8 = lane >> 3, r8 = lane & 7;
    const int wm = wid & 1, wn = wid >> 1;
    const int row0 = blockIdx.y * BM, col0 = blockIdx.x * BN;

    const __half* Arow = A  + (size_t)row0 * lda;
    const __half* Brow = Bg + (size_t)col0 * ldb;

    const uint32_t sA = cvta_smem(As);
    const uint32_t sB = cvta_smem(Bs);
    const int ldRow = tid >> 3;
    const int ldCol = (tid & 7) * 8;

    const int rowA = wm * 64 + (q8 & 1) * 8 + r8;
    const int colA = (q8 >> 1) * 8;
    const int rowB = wn * 64 + (q8 >> 1) * 8 + r8;
    const int colB = (q8 & 1) * 8;

    auto load_tile = [&](int t) {
        const int st = t % ST;
        const int kt = t * BK;
        #pragma unroll
        for (int i = 0; i < 8; i++) {
            int r = i * 16 + ldRow;
            cpasync16(sA + (uint32_t)((st * BM + r) * LDH + ldCol) * 2,
                      Arow + (size_t)r * lda + kt + ldCol);
        }
        #pragma unroll
        for (int i = 0; i < 8; i++) {
            int r = i * 16 + ldRow;
            cpasync16(sB + (uint32_t)((st * BN + r) * LDH + ldCol) * 2,
                      Brow + (size_t)r * ldb + kt + ldCol);
        }
    };

    const int nT = K / BK;             // >= 16 for all our shapes
    load_tile(0); cp_commit();
    load_tile(1); cp_commit();
    load_tile(2); cp_commit();
    cp_wait<2>();
    __syncthreads();

    float acc[4][8][4];
    #pragma unroll
    for (int i = 0; i < 4; i++)
        #pragma unroll
        for (int j = 0; j < 8; j++)
            #pragma unroll
            for (int r = 0; r < 4; r++) acc[i][j][r] = 0.f;

    for (int t = 0; t < nT; t++) {
        const uint32_t aBase = sA + (uint32_t)((t % ST) * BM * LDH) * 2;
        const uint32_t bBase = sB + (uint32_t)((t % ST) * BN * LDH) * 2;

        #pragma unroll
        for (int ks = 0; ks < 4; ks++) {
            uint32_t af[4][4], bf[8][2];
            #pragma unroll
            for (int i = 0; i < 4; i++)
                ldsm_x4(af[i][0], af[i][1], af[i][2], af[i][3],
                        aBase + (uint32_t)((rowA + 16 * i) * LDH + colA + ks * 16) * 2);
            #pragma unroll
            for (int p = 0; p < 4; p++) {
                uint32_t b0, b1, b2, b3;
                ldsm_x4(b0, b1, b2, b3,
                        bBase + (uint32_t)((rowB + 16 * p) * LDH + colB + ks * 16) * 2);
                bf[2*p][0] = b0; bf[2*p][1] = b1;
                bf[2*p+1][0] = b2; bf[2*p+1][1] = b3;
            }
            #pragma unroll
            for (int i = 0; i < 4; i++)
                #pragma unroll
                for (int j = 0; j < 8; j++)
                    mma_f16(acc[i][j], af[i], bf[j]);
        }

        // all warps done reading stage t%3 before it is overwritten by t+3
        __syncthreads();
        if (t + 3 < nT) load_tile(t + 3);
        cp_commit();
        cp_wait<2>();          // g_{t+1} complete; g_{t+2}, g_{t+3} stay in flight
        __syncthreads();       // cross-thread visibility of g_{t+1} data
    }

    #pragma unroll
    for (int i = 0; i < 4; i++) {
        #pragma unroll
        for (int j = 0; j < 8; j++) {
            int col = col0 + wn * 64 + 8 * j + 2 * c4;
            #pragma unroll
            for (int h = 0; h < 2; h++) {
                int row = row0 + wm * 64 + 16 * i + g + 8 * h;
                float v0 = acc[i][j][2 * h + 0];
                float v1 = acc[i][j][2 * h + 1];
                if (EPI == 1) {
                    const float* rr = resid + (size_t)row * ldc + col;
                    const float* gg = gate + (size_t)(row / rows_per_b) * gate_ld + col;
                    v0 = rr[0] + gg[0] * v0;
                    v1 = rr[1] + gg[1] * v1;
                }
                if (OH == 1) {
                    *(__half2*)((__half*)Cv + (size_t)row * ldc + col) =
                        __floats2half2_rn(v0, v1);
                } else if (OH == 0) {
                    *(float2*)((float*)Cv + (size_t)row * ldc + col) = make_float2(v0, v1);
                } else {
                    float sv = (v0 / (1.0f + __expf(-v0))) * v1;
                    ((__half*)Cv)[(size_t)row * (ldc >> 1) + (col >> 1)] = __float2half_rn(sv);
                }
            }
        }
    }
}

// ---------------- fused flash attention (fp16 mma, register-resident P) ----------
// 3-stage KV ring with 2-deep prefetch.
__global__ void __launch_bounds__(256, 2)
flash_kernel(const __half* __restrict__ Qg, const __half* __restrict__ Kg,
             const __half* __restrict__ Vg, __half* __restrict__ Og,
             int Skv, int ldq, int ldkv)
{
    const int h = blockIdx.y, b = blockIdx.z;
    const int n0 = blockIdx.x * 128;
    const __half* Qb = Qg + (size_t)b * Nn * ldq + (size_t)n0 * ldq + h * HDh;
    const __half* Kb = Kg + (size_t)b * Skv * ldkv + h * HDh;
    const __half* Vb = Vg + (size_t)b * Skv * ldkv + h * HDh;
    __half* Ob = Og + (size_t)b * Nn * INNER + (size_t)n0 * INNER + h * HDh;

    extern __shared__ __half fsm[];
    __half* Qs = fsm;                      // [128][72]
    __half* Ks = Qs + 128 * 72;            // [3][64][72]
    __half* Vs = Ks + 3 * 64 * 72;         // [3][64][72]

    const int tid = threadIdx.x, wid = tid >> 5, lane = tid & 31;
    const int g = lane >> 2, c4 = lane & 3;
    const int q8 = lane >> 3, r8 = lane & 7;

    const uint32_t sK = cvta_smem(Ks);
    const uint32_t sV = cvta_smem(Vs);

    {
        const __half2 sc2 = __floats2half2_rn(0.125f, 0.125f);
        #pragma unroll
        for (int it = 0; it < 4; it++) {
            int idx = it * 256 + tid;
            int r = idx >> 3, c = (idx & 7) * 8;
            uint4 qv = *(const uint4*)(Qb + (size_t)r * ldq + c);
            __half2* hp = (__half2*)&qv;
            hp[0] = __hmul2(hp[0], sc2);
            hp[1] = __hmul2(hp[1], sc2);
            hp[2] = __hmul2(hp[2], sc2);
            hp[3] = __hmul2(hp[3], sc2);
            *(uint4*)(Qs + r * 72 + c) = qv;
        }
    }

    auto loadKV = [&](int t) {
        const int buf = t % 3;
        const __half* Ksrc = Kb + (size_t)(t * 64) * ldkv;
        const __half* Vsrc = Vb + (size_t)(t * 64) * ldkv;
        #pragma unroll
        for (int it = 0; it < 2; it++) {
            int idx = it * 256 + tid;
            int r = idx >> 3, c = (idx & 7) * 8;
            cpasync16(sK + (uint32_t)((buf * 64 + r) * 72 + c) * 2, Ksrc + (size_t)r * ldkv + c);
            cpasync16(sV + (uint32_t)((buf * 64 + r) * 72 + c) * 2, Vsrc + (size_t)r * ldkv + c);
        }
    };

    const int nT = Skv / 64;              // 8 (SA) or 32 (CA)
    loadKV(0); cp_commit();
    if (nT > 1) loadKV(1);
    cp_commit();
    if (nT > 2) loadKV(2);
    cp_commit();
    cp_wait<2>();
    __syncthreads();

    uint32_t qf[4][4];
    {
        const uint32_t* Qw = (const uint32_t*)(Qs + wid * 16 * 72);
        #pragma unroll
        for (int ks = 0; ks < 4; ks++) {
            qf[ks][0] = Qw[(g    ) * 36 + 8 * ks + c4];
            qf[ks][1] = Qw[(g + 8) * 36 + 8 * ks + c4];
            qf[ks][2] = Qw[(g    ) * 36 + 8 * ks + c4 + 4];
            qf[ks][3] = Qw[(g + 8) * 36 + 8 * ks + c4 + 4];
        }
    }

    float o[8][4];
    #pragma unroll
    for (int j = 0; j < 8; j++)
        #pragma unroll
        for (int r = 0; r < 4; r++) o[j][r] = 0.f;
    float m0 = -1e30f, m1 = -1e30f, l0 = 0.f, l1 = 0.f;

    const int rowK = (q8 >> 1) * 8 + r8;
    const int colK = (q8 & 1) * 8;
    const int rowV = lane & 15;
    const int colV = (lane >> 4) * 8;

    for (int t = 0; t < nT; t++) {
        const int buf = t % 3;

        float s[8][4];
        #pragma unroll
        for (int j = 0; j < 8; j++)
            #pragma unroll
            for (int r = 0; r < 4; r++) s[j][r] = 0.f;

        const uint32_t sKb = sK + (uint32_t)(buf * 64 * 72) * 2;
        #pragma unroll
        for (int ks = 0; ks < 4; ks++) {
            #pragma unroll
            for (int p = 0; p < 4; p++) {
                uint32_t b0, b1, b2, b3;
                ldsm_x4(b0, b1, b2, b3,
                        sKb + (uint32_t)((16 * p + rowK) * 72 + colK + ks * 16) * 2);
                uint32_t f0[2] = {b0, b1}, f1[2] = {b2, b3};
                mma_f16(s[2*p],   qf[ks], f0);
                mma_f16(s[2*p+1], qf[ks], f1);
            }
        }

        float rm0 = -1e30f, rm1 = -1e30f;
        #pragma unroll
        for (int j = 0; j < 8; j++) {
            rm0 = fmaxf(rm0, fmaxf(s[j][0], s[j][1]));
            rm1 = fmaxf(rm1, fmaxf(s[j][2], s[j][3]));
        }
        rm0 = fmaxf(rm0, __shfl_xor_sync(0xffffffff, rm0, 1));
        rm0 = fmaxf(rm0, __shfl_xor_sync(0xffffffff, rm0, 2));
        rm1 = fmaxf(rm1, __shfl_xor_sync(0xffffffff, rm1, 1));
        rm1 = fmaxf(rm1, __shfl_xor_sync(0xffffffff, rm1, 2));

        float mn0 = fmaxf(m0, rm0), mn1 = fmaxf(m1, rm1);
        float f0 = __expf(m0 - mn0), f1 = __expf(m1 - mn1);
        m0 = mn0; m1 = mn1;

        float sum0 = 0.f, sum1 = 0.f;
        #pragma unroll
        for (int j = 0; j < 8; j++) {
            s[j][0] = __expf(s[j][0] - mn0);
            s[j][1] = __expf(s[j][1] - mn0);
            s[j][2] = __expf(s[j][2] - mn1);
            s[j][3] = __expf(s[j][3] - mn1);
            sum0 += s[j][0] + s[j][1];
            sum1 += s[j][2] + s[j][3];
        }
        sum0 += __shfl_xor_sync(0xffffffff, sum0, 1);
        sum0 += __shfl_xor_sync(0xffffffff, sum0, 2);
        sum1 += __shfl_xor_sync(0xffffffff, sum1, 1);
        sum1 += __shfl_xor_sync(0xffffffff, sum1, 2);
        l0 = l0 * f0 + sum0;
        l1 = l1 * f1 + sum1;

        #pragma unroll
        for (int j = 0; j < 8; j++) {
            o[j][0] *= f0; o[j][1] *= f0;
            o[j][2] *= f1; o[j][3] *= f1;
        }

        const uint32_t sVb = sV + (uint32_t)(buf * 64 * 72) * 2;
        #pragma unroll
        for (int jk = 0; jk < 4; jk++) {
            uint32_t af[4];
            af[0] = pack_h2(s[2*jk][0],   s[2*jk][1]);
            af[1] = pack_h2(s[2*jk][2],   s[2*jk][3]);
            af[2] = pack_h2(s[2*jk+1][0], s[2*jk+1][1]);
            af[3] = pack_h2(s[2*jk+1][2], s[2*jk+1][3]);
            const uint32_t base = sVb + (uint32_t)((16 * jk + rowV) * 72 + colV) * 2;
            #pragma unroll
            for (int jp = 0; jp < 4; jp++) {
                uint32_t b0, b1, b2, b3;
                ldsm_x4_trans(b0, b1, b2, b3, base + (uint32_t)(16 * jp) * 2);
                uint32_t f0[2] = {b0, b1}, f1[2] = {b2, b3};
                mma_f16(o[2*jp],   af, f0);
                mma_f16(o[2*jp+1], af, f1);
            }
        }

        // 2-deep refill of the ring
        __syncthreads();
        if (t + 3 < nT) loadKV(t + 3);
        cp_commit();
        cp_wait<2>();
        __syncthreads();
    }

    float inv0 = 1.0f / l0, inv1 = 1.0f / l1;
    #pragma unroll
    for (int j = 0; j < 8; j++) {
        int col = 8 * j + 2 * c4;
        *(__half2*)(Ob + (size_t)(wid * 16 + g    ) * INNER + col) =
            __floats2half2_rn(o[j][0] * inv0, o[j][1] * inv0);
        *(__half2*)(Ob + (size_t)(wid * 16 + g + 8) * INNER + col) =
            __floats2half2_rn(o[j][2] * inv1, o[j][3] * inv1);
    }
}

// ---------------- fp32 -> fp16 conversion ----------------------------------------
__device__ __forceinline__ uint2 cvt4(float4 t) {
    __half2 lo = __floats2half2_rn(t.x, t.y);
    __half2 hi = __floats2half2_rn(t.z, t.w);
    uint2 o;
    o.x = *(uint32_t*)&lo;
    o.y = *(uint32_t*)&hi;
    return o;
}
__global__ void f32_to_f16_kernel(const float4* __restrict__ in, uint2* __restrict__ out, int n4)
{
    int i = blockIdx.x * blockDim.x + threadIdx.x;
    if (i < n4) out[i] = cvt4(in[i]);
}
__global__ void f32_to_f16_ileave(const float4* __restrict__ gsrc, const float4* __restrict__ usrc,
                                  uint2* __restrict__ out, int n4, int cols4)
{
    int i = blockIdx.x * blockDim.x + threadIdx.x;
    if (i < n4) {
        int r = i / cols4, c = i - r * cols4;
        out[(size_t)(2 * r) * cols4 + c]     = cvt4(gsrc[i]);
        out[(size_t)(2 * r + 1) * cols4 + c] = cvt4(usrc[i]);
    }
}

// ---------------- modulation (fp32) ----------------------------------------------
__global__ void mod_kernel(const float* __restrict__ cond,
                           const float* __restrict__ mw0, const float* __restrict__ mb0,
                           const float* __restrict__ mw1, const float* __restrict__ mb1,
                           const float* __restrict__ mw2, const float* __restrict__ mb2,
                           float* __restrict__ mods)
{
    __shared__ float cs[Bb * Dm];
    for (int i = threadIdx.x; i < Bb * Dm; i += blockDim.x) cs[i] = cond[i];
    __syncthreads();

    int warp = threadIdx.x >> 5, lane = threadIdx.x & 31;
    int j = blockIdx.x * 8 + warp;
    int norm = j / (3*Dm), jj = j - norm * (3*Dm);
    const float* mw = (norm == 0) ? mw0 : (norm == 1) ? mw1 : mw2;
    const float* mb = (norm == 0) ? mb0 : (norm == 1) ? mb1 : mb2;

    float acc[Bb];
    #pragma unroll
    for (int b = 0; b < Bb; b++) acc[b] = 0.f;
    const float* wrow = mw + (size_t)jj * Dm;
    for (int d = lane; d < Dm; d += 32) {
        float w = wrow[d];
        #pragma unroll
        for (int b = 0; b < Bb; b++) acc[b] = fmaf(w, cs[b*Dm + d], acc[b]);
    }
    #pragma unroll
    for (int b = 0; b < Bb; b++)
        #pragma unroll
        for (int off = 16; off > 0; off >>= 1)
            acc[b] += __shfl_xor_sync(0xffffffff, acc[b], off);
    if (lane < Bb)
        mods[(size_t)norm * Bb * 3*Dm + lane * 3*Dm + jj] = acc[lane] + mb[jj];
}

// ---------------- adaRMS norm (fp16 output) --------------------------------------
__global__ void rmsnorm_kernel(const float* __restrict__ x, const float* __restrict__ w,
                               const float* __restrict__ mod_base,
                               __half* __restrict__ out)
{
    int row = blockIdx.x;
    int b   = row / Nn;
    const float* xr = x + (size_t)row * Dm;
    const float* ms = mod_base + b * 3*Dm;

    float ss = 0.f;
    for (int i = threadIdx.x; i < Dm; i += blockDim.x) { float t = xr[i]; ss = fmaf(t,t,ss); }
    #pragma unroll
    for (int off = 16; off > 0; off >>= 1) ss += __shfl_xor_sync(0xffffffff, ss, off);
    __shared__ float red[8];
    if ((threadIdx.x & 31) == 0) red[threadIdx.x >> 5] = ss;
    __syncthreads();
    if (threadIdx.x < 8) {
        float v = red[threadIdx.x];
        #pragma unroll
        for (int off = 4; off > 0; off >>= 1) v += __shfl_xor_sync(0xff, v, off);
        if (threadIdx.x == 0) red[0] = v;
    }
    __syncthreads();
    float rn = rsqrtf(red[0] * (1.0f/Dm) + EPSf);

    __half* orow = out + (size_t)row * Dm;
    for (int i = threadIdx.x; i < Dm/2; i += blockDim.x) {
        int i2 = 2 * i;
        float a = xr[i2]   * rn * w[i2]   * (1.0f + ms[i2])   + ms[Dm + i2];
        float c = xr[i2+1] * rn * w[i2+1] * (1.0f + ms[i2+1]) + ms[Dm + i2+1];
        *(__half2*)(orow + i2) = __floats2half2_rn(a, c);
    }
}

// ---------------- host orchestration -------------------------------------------
static void* symv(const void* s) { void* p = nullptr; cudaGetSymbolAddress(&p, s); return p; }

template<int EPI,int OH>
static void gemm_h(cudaStream_t st, const __half* A, const __half* W, void* C,
                   int M, int N, int K,
                   const float* resid, const float* gate, int gate_ld, int rpb)
{
    size_t sm = (size_t)3 * (128 + 128) * 72 * sizeof(__half);   // 110592
    cudaFuncSetAttribute(gemm_f16<EPI,OH>,
                         cudaFuncAttributeMaxDynamicSharedMemorySize, (int)sm);
    gemm_f16<EPI,OH><<<dim3(N/128, M/128), 128, sm, st>>>(
        A, W, C, K, K, K, N, resid, gate, gate_ld, rpb);
}

static void cvt_to(cudaStream_t st, __half* dst, const float* src, int n)
{
    f32_to_f16_kernel<<<(n/4 + 255)/256, 256, 0, st>>>((const float4*)src, (uint2*)dst, n/4);
}

static void launch_flash(const __half* q, const __half* k, const __half* v, __half* o,
                         int Skv, int ldq, int ldkv)
{
    size_t sm = (size_t)(128*72 + 3*64*72 + 3*64*72) * sizeof(__half);  // 73728
    cudaFuncSetAttribute(flash_kernel, cudaFuncAttributeMaxDynamicSharedMemorySize, (int)sm);
    flash_kernel<<<dim3(Nn/128, Hh, Bb), 256, sm>>>(q, k, v, o, Skv, ldq, ldkv);
}

extern "C" void kernel_launch(void* const* d_in, const int* in_sizes, int n_in,
                              void* d_out, int out_size)
{
    const float* x       = (const float*)d_in[0];
    const float* context = (const float*)d_in[1];
    const float* cond    = (const float*)d_in[2];
    const float* n1_w  = (const float*)d_in[3];
    const float* n1_mw = (const float*)d_in[4];
    const float* n1_mb = (const float*)d_in[5];
    const float* n2_w  = (const float*)d_in[6];
    const float* n2_mw = (const float*)d_in[7];
    const float* n2_mb = (const float*)d_in[8];
    const float* n3_w  = (const float*)d_in[9];
    const float* n3_mw = (const float*)d_in[10];
    const float* n3_mb = (const float*)d_in[11];
    const float* sa_q  = (const float*)d_in[12];
    const float* sa_k  = (const float*)d_in[13];
    const float* sa_v  = (const float*)d_in[14];
    const float* sa_o  = (const float*)d_in[15];
    const float* ca_q  = (const float*)d_in[16];
    const float* ca_k  = (const float*)d_in[17];
    const float* ca_v  = (const float*)d_in[18];
    const float* ca_o  = (const float*)d_in[19];
    const float* ff_gate = (const float*)d_in[20];
    const float* ff_up   = (const float*)d_in[21];
    const float* ff_down = (const float*)d_in[22];
    float* out = (float*)d_out;

    float*  mods   = (float*)symv(d_mods);
    __half* normed = (__half*)symv(d_normed);
    __half* qkv    = (__half*)symv(d_qkv);
    __half* kv     = (__half*)symv(d_kv);
    __half* ao     = (__half*)symv(d_attno);
    float*  x1     = (float*)symv(d_x1);
    float*  x2     = (float*)symv(d_x2);
    __half* hb     = (__half*)symv(d_hbuf);
    __half* ctx    = (__half*)symv(d_ctx);
    __half* wr     = (__half*)symv(d_wrnd);

    const int MQ = Bb * Nn;

    static cudaStream_t s2 = nullptr, s3 = nullptr;
    static cudaEvent_t evFork = nullptr, evKV = nullptr, evW3 = nullptr;
    if (s2 == nullptr) {
        cudaStreamCreateWithFlags(&s2, cudaStreamNonBlocking);
        cudaStreamCreateWithFlags(&s3, cudaStreamNonBlocking);
        cudaEventCreateWithFlags(&evFork, cudaEventDisableTiming);
        cudaEventCreateWithFlags(&evKV, cudaEventDisableTiming);
        cudaEventCreateWithFlags(&evW3, cudaEventDisableTiming);
    }

    // ---- fork ----
    cudaEventRecord(evFork, 0);
    cudaStreamWaitEvent(s2, evFork, 0);
    cudaStreamWaitEvent(s3, evFork, 0);

    // s2: CA K/V branch (converts + the big KV GEMM)
    cvt_to(s2, wr + W_CAK,             ca_k, INNER*Cm);
    cvt_to(s2, wr + W_CAK + 2048*1024, ca_v, INNER*Cm);
    cvt_to(s2, ctx, context, Bb*Ss*Cm);
    gemm_h<0,1>(s2, ctx, wr + W_CAK, kv, Bb*Ss, 2*INNER, Cm, nullptr, nullptr, 0, 1);
    cudaEventRecord(evKV, s2);

    // s3: non-critical weight converts
    cvt_to(s3, wr + W_SAO, sa_o, Dm*INNER);
    cvt_to(s3, wr + W_CAQ, ca_q, INNER*Dm);
    cvt_to(s3, wr + W_CAO, ca_o, Dm*INNER);
    f32_to_f16_ileave<<<(MLPm*Dm/4 + 255)/256, 256, 0, s3>>>(
        (const float4*)ff_gate, (const float4*)ff_up,
        (uint2*)(wr + W_FFGU), MLPm*Dm/4, Dm/4);
    cvt_to(s3, wr + W_FFD, ff_down, Dm*MLPm);
    cudaEventRecord(evW3, s3);

    // main stream: minimal prefix
    cvt_to(0, wr + W_SAQ,             sa_q, INNER*Dm);
    cvt_to(0, wr + W_SAQ + 1024*1024, sa_k, INNER*Dm);
    cvt_to(0, wr + W_SAQ + 2048*1024, sa_v, INNER*Dm);
    mod_kernel<<<(3*3*Dm)/8, 256>>>(cond, n1_mw, n1_mb, n2_mw, n2_mb, n3_mw, n3_mb, mods);

    // ===================== Self attention =====================
    rmsnorm_kernel<<<MQ, 256>>>(x, n1_w, mods + 0*Bb*3*Dm, normed);
    gemm_h<0,1>(0, normed, wr + W_SAQ, qkv, MQ, 3*INNER, Dm, nullptr, nullptr, 0, 1);
    launch_flash(qkv, qkv + INNER, qkv + 2*INNER, ao, Nn, 3*INNER, 3*INNER);
    cudaStreamWaitEvent(0, evW3, 0);
    gemm_h<1,0>(0, ao, wr + W_SAO, x1, MQ, Dm, INNER, x, mods + 0*Bb*3*Dm + 2*Dm, 3*Dm, Nn);

    // ===================== Cross attention =====================
    rmsnorm_kernel<<<MQ, 256>>>(x1, n2_w, mods + 1*Bb*3*Dm, normed);
    gemm_h<0,1>(0, normed, wr + W_CAQ, qkv, MQ, INNER, Dm, nullptr, nullptr, 0, 1);
    cudaStreamWaitEvent(0, evKV, 0);
    launch_flash(qkv, kv, kv + INNER, ao, Ss, INNER, 2*INNER);
    gemm_h<1,0>(0, ao, wr + W_CAO, x2, MQ, Dm, INNER, x1, mods + 1*Bb*3*Dm + 2*Dm, 3*Dm, Nn);

    // ===================== FFN =====================
    rmsnorm_kernel<<<MQ, 256>>>(x2, n3_w, mods + 2*Bb*3*Dm, normed);
    gemm_h<0,2>(0, normed, wr + W_FFGU, hb, MQ, 2*MLPm, Dm, nullptr, nullptr, 0, 1);
    gemm_h<1,0>(0, hb, wr + W_FFD, out, MQ, Dm, MLPm, x2, mods + 2*Bb*3*Dm + 2*Dm, 3*Dm, Nn);
}

// round 14
// speedup vs baseline: 1.0149x; 1.0149x over previous
#include <cuda_runtime.h>
#include <cuda_fp16.h>
#include <math.h>
#include <stdint.h>

// Problem dims
#define Dm    1024
#define Cm    2048
#define MLPm  4096
#define Hh    16
#define HDh   64
#define Bb    8
#define Nn    512
#define Ss    2048
#define INNER (Hh*HDh)   // 1024
#define EPSf  1e-6f

// ---------------- scratch (static device allocations) ---------------------------
__device__ __align__(16) float  d_mods  [3 * Bb * 3 * Dm];
__device__ __align__(16) __half d_normed[Bb * Nn * Dm];
__device__ __align__(16) __half d_qkv   [Bb * Nn * 3 * INNER];
__device__ __align__(16) __half d_kv    [(size_t)Bb * Ss * 2 * INNER];
__device__ __align__(16) __half d_attno [Bb * Nn * INNER];
__device__ __align__(16) float  d_x1    [Bb * Nn * Dm];
__device__ __align__(16) float  d_x2    [Bb * Nn * Dm];
__device__ __align__(16) __half d_hbuf  [Bb * Nn * MLPm];
__device__ __align__(16) __half d_ctx   [(size_t)Bb * Ss * Cm];
__device__ __align__(16) __half d_wrnd  [22 * 1024 * 1024];

// weight offsets (elements); adjacency is load-bearing for fused GEMMs:
// [SAQ|SAK|SAV] 3072x1024, [CAK|CAV] 2048x2048, FFGU interleaved 8192x1024
#define W_SAQ  (0)
#define W_SAO  (3*1024*1024)
#define W_CAQ  (4*1024*1024)
#define W_CAK  (5*1024*1024)
#define W_CAO  (9*1024*1024)
#define W_FFGU (10*1024*1024)
#define W_FFD  (18*1024*1024)

// ---------------- helpers ---------------------------------------------------------
__device__ __forceinline__ void mma_f16(float* c, const uint32_t* a, const uint32_t* b) {
    asm volatile(
        "mma.sync.aligned.m16n8k16.row.col.f32.f16.f16.f32 "
        "{%0,%1,%2,%3}, {%4,%5,%6,%7}, {%8,%9}, {%0,%1,%2,%3};\n"
        : "+f"(c[0]), "+f"(c[1]), "+f"(c[2]), "+f"(c[3])
        : "r"(a[0]), "r"(a[1]), "r"(a[2]), "r"(a[3]), "r"(b[0]), "r"(b[1]));
}

__device__ __forceinline__ void cpasync16(uint32_t saddr, const void* gptr) {
    asm volatile("cp.async.cg.shared.global [%0], [%1], 16;\n" :: "r"(saddr), "l"(gptr));
}
__device__ __forceinline__ void cp_commit() { asm volatile("cp.async.commit_group;\n"); }
template<int n> __device__ __forceinline__ void cp_wait() {
    asm volatile("cp.async.wait_group %0;\n" :: "n"(n));
}
__device__ __forceinline__ uint32_t cvta_smem(const void* p) {
    uint32_t a;
    asm("{ .reg .u64 t; cvta.to.shared.u64 t, %1; cvt.u32.u64 %0, t; }" : "=r"(a) : "l"(p));
    return a;
}
__device__ __forceinline__ void ldsm_x4(uint32_t& r0, uint32_t& r1, uint32_t& r2, uint32_t& r3,
                                        uint32_t addr) {
    asm volatile("ldmatrix.sync.aligned.m8n8.x4.shared.b16 {%0,%1,%2,%3}, [%4];"
                 : "=r"(r0), "=r"(r1), "=r"(r2), "=r"(r3) : "r"(addr));
}
__device__ __forceinline__ void ldsm_x4_trans(uint32_t& r0, uint32_t& r1, uint32_t& r2, uint32_t& r3,
                                              uint32_t addr) {
    asm volatile("ldmatrix.sync.aligned.m8n8.x4.trans.shared.b16 {%0,%1,%2,%3}, [%4];"
                 : "=r"(r0), "=r"(r1), "=r"(r2), "=r"(r3) : "r"(addr));
}
__device__ __forceinline__ uint32_t pack_h2(float a, float b) {
    __half2 h = __floats2half2_rn(a, b);
    return *(uint32_t*)&h;
}

// ---------------- fp16 NT GEMM: C(M,N) = A(M,K) @ B(N,K)^T ----------------------
// 128x128 CTA tile, 128 threads (4 warps 2x2, warp tile 64x64), BK=64,
// row pad 72 halves, 3-stage cp.async ring, 2 CTAs/SM. Loads issued at TOP of
// the loop so DMA of tile t+2 overlaps compute of tile t (single barrier/tile).
// EPI==1: add resid + gate[(row/rows_per_b)*gate_ld+col]*acc (float out)
// OH: 0 = float out, 1 = half out, 2 = silu-pair: h[row][col/2] = silu(even)*odd
template<int EPI,int OH>
__global__ void __launch_bounds__(128, 2)
gemm_f16(const __half* __restrict__ A, const __half* __restrict__ Bg, void* __restrict__ Cv,
         int K, int lda, int ldb, int ldc,
         const float* __restrict__ resid, const float* __restrict__ gate,
         int gate_ld, int rows_per_b)
{
    constexpr int BM = 128, BN = 128, BK = 64, LDH = 72, ST = 3;

    extern __shared__ __half hsm[];
    __half* As = hsm;
    __half* Bs = hsm + ST * BM * LDH;

    const int tid = threadIdx.x, wid = tid >> 5, lane = tid & 31;
    const int g = lane >> 2, c4 = lane & 3;
    const int q8 = lane >> 3, r8 = lane & 7;
    const int wm = wid & 1, wn = wid >> 1;
    const int row0 = blockIdx.y * BM, col0 = blockIdx.x * BN;

    const __half* Arow = A  + (size_t)row0 * lda;
    const __half* Brow = Bg + (size_t)col0 * ldb;

    const uint32_t sA = cvta_smem(As);
    const uint32_t sB = cvta_smem(Bs);
    const int ldRow = tid >> 3;
    const int ldCol = (tid & 7) * 8;

    const int rowA = wm * 64 + (q8 & 1) * 8 + r8;
    const int colA = (q8 >> 1) * 8;
    const int rowB = wn * 64 + (q8 >> 1) * 8 + r8;
    const int colB = (q8 & 1) * 8;

    auto load_tile = [&](int t) {
        const int st = t % ST;
        const int kt = t * BK;
        #pragma unroll
        for (int i = 0; i < 8; i++) {
            int r = i * 16 + ldRow;
            cpasync16(sA + (uint32_t)((st * BM + r) * LDH + ldCol) * 2,
                      Arow + (size_t)r * lda + kt + ldCol);
        }
        #pragma unroll
        for (int i = 0; i < 8; i++) {
            int r = i * 16 + ldRow;
            cpasync16(sB + (uint32_t)((st * BN + r) * LDH + ldCol) * 2,
                      Brow + (size_t)r * ldb + kt + ldCol);
        }
    };

    const int nT = K / BK;
    load_tile(0); cp_commit();
    load_tile(1); cp_commit();
    cp_wait<1>();
    __syncthreads();

    float acc[4][8][4];
    #pragma unroll
    for (int i = 0; i < 4; i++)
        #pragma unroll
        for (int j = 0; j < 8; j++)
            #pragma unroll
            for (int r = 0; r < 4; r++) acc[i][j][r] = 0.f;

    for (int t = 0; t < nT; t++) {
        // issue next-next tile first: DMA overlaps this tile's compute.
        // stage (t+2)%3 == (t-1)%3 was released by the barrier at end of t-1.
        if (t + 2 < nT) load_tile(t + 2);
        cp_commit();

        const uint32_t aBase = sA + (uint32_t)((t % ST) * BM * LDH) * 2;
        const uint32_t bBase = sB + (uint32_t)((t % ST) * BN * LDH) * 2;

        #pragma unroll
        for (int ks = 0; ks < 4; ks++) {
            uint32_t af[4][4], bf[8][2];
            #pragma unroll
            for (int i = 0; i < 4; i++)
                ldsm_x4(af[i][0], af[i][1], af[i][2], af[i][3],
                        aBase + (uint32_t)((rowA + 16 * i) * LDH + colA + ks * 16) * 2);
            #pragma unroll
            for (int p = 0; p < 4; p++) {
                uint32_t b0, b1, b2, b3;
                ldsm_x4(b0, b1, b2, b3,
                        bBase + (uint32_t)((rowB + 16 * p) * LDH + colB + ks * 16) * 2);
                bf[2*p][0] = b0; bf[2*p][1] = b1;
                bf[2*p+1][0] = b2; bf[2*p+1][1] = b3;
            }
            #pragma unroll
            for (int i = 0; i < 4; i++)
                #pragma unroll
                for (int j = 0; j < 8; j++)
                    mma_f16(acc[i][j], af[i], bf[j]);
        }

        cp_wait<1>();          // g_{t+1} complete (had a full compute-phase)
        __syncthreads();       // release stage t%3 for reuse + data visibility
    }

    #pragma unroll
    for (int i = 0; i < 4; i++) {
        #pragma unroll
        for (int j = 0; j < 8; j++) {
            int col = col0 + wn * 64 + 8 * j + 2 * c4;
            #pragma unroll
            for (int h = 0; h < 2; h++) {
                int row = row0 + wm * 64 + 16 * i + g + 8 * h;
                float v0 = acc[i][j][2 * h + 0];
                float v1 = acc[i][j][2 * h + 1];
                if (EPI == 1) {
                    const float* rr = resid + (size_t)row * ldc + col;
                    const float* gg = gate + (size_t)(row / rows_per_b) * gate_ld + col;
                    v0 = rr[0] + gg[0] * v0;
                    v1 = rr[1] + gg[1] * v1;
                }
                if (OH == 1) {
                    *(__half2*)((__half*)Cv + (size_t)row * ldc + col) =
                        __floats2half2_rn(v0, v1);
                } else if (OH == 0) {
                    *(float2*)((float*)Cv + (size_t)row * ldc + col) = make_float2(v0, v1);
                } else {
                    float sv = (v0 / (1.0f + __expf(-v0))) * v1;
                    ((__half*)Cv)[(size_t)row * (ldc >> 1) + (col >> 1)] = __float2half_rn(sv);
                }
            }
        }
    }
}

// ---------------- fused flash attention (fp16 mma, register-resident P) ----------
// R12 structure: 2-buffer KV ring, loads issued before compute, wait<0> at end.
__global__ void __launch_bounds__(256, 2)
flash_kernel(const __half* __restrict__ Qg, const __half* __restrict__ Kg,
             const __half* __restrict__ Vg, __half* __restrict__ Og,
             int Skv, int ldq, int ldkv)
{
    const int h = blockIdx.y, b = blockIdx.z;
    const int n0 = blockIdx.x * 128;
    const __half* Qb = Qg + (size_t)b * Nn * ldq + (size_t)n0 * ldq + h * HDh;
    const __half* Kb = Kg + (size_t)b * Skv * ldkv + h * HDh;
    const __half* Vb = Vg + (size_t)b * Skv * ldkv + h * HDh;
    __half* Ob = Og + (size_t)b * Nn * INNER + (size_t)n0 * INNER + h * HDh;

    extern __shared__ __half fsm[];
    __half* Qs = fsm;                      // [128][72]
    __half* Ks = Qs + 128 * 72;            // [2][64][72]
    __half* Vs = Ks + 2 * 64 * 72;         // [2][64][72]

    const int tid = threadIdx.x, wid = tid >> 5, lane = tid & 31;
    const int g = lane >> 2, c4 = lane & 3;
    const int q8 = lane >> 3, r8 = lane & 7;

    const uint32_t sK = cvta_smem(Ks);
    const uint32_t sV = cvta_smem(Vs);

    {
        const __half2 sc2 = __floats2half2_rn(0.125f, 0.125f);
        #pragma unroll
        for (int it = 0; it < 4; it++) {
            int idx = it * 256 + tid;
            int r = idx >> 3, c = (idx & 7) * 8;
            uint4 qv = *(const uint4*)(Qb + (size_t)r * ldq + c);
            __half2* hp = (__half2*)&qv;
            hp[0] = __hmul2(hp[0], sc2);
            hp[1] = __hmul2(hp[1], sc2);
            hp[2] = __hmul2(hp[2], sc2);
            hp[3] = __hmul2(hp[3], sc2);
            *(uint4*)(Qs + r * 72 + c) = qv;
        }
    }

    auto loadKV = [&](int t, int buf) {
        const __half* Ksrc = Kb + (size_t)(t * 64) * ldkv;
        const __half* Vsrc = Vb + (size_t)(t * 64) * ldkv;
        #pragma unroll
        for (int it = 0; it < 2; it++) {
            int idx = it * 256 + tid;
            int r = idx >> 3, c = (idx & 7) * 8;
            cpasync16(sK + (uint32_t)((buf * 64 + r) * 72 + c) * 2, Ksrc + (size_t)r * ldkv + c);
            cpasync16(sV + (uint32_t)((buf * 64 + r) * 72 + c) * 2, Vsrc + (size_t)r * ldkv + c);
        }
    };
    loadKV(0, 0);
    cp_commit();
    cp_wait<0>();
    __syncthreads();

    uint32_t qf[4][4];
    {
        const uint32_t* Qw = (const uint32_t*)(Qs + wid * 16 * 72);
        #pragma unroll
        for (int ks = 0; ks < 4; ks++) {
            qf[ks][0] = Qw[(g    ) * 36 + 8 * ks + c4];
            qf[ks][1] = Qw[(g + 8) * 36 + 8 * ks + c4];
            qf[ks][2] = Qw[(g    ) * 36 + 8 * ks + c4 + 4];
            qf[ks][3] = Qw[(g + 8) * 36 + 8 * ks + c4 + 4];
        }
    }

    float o[8][4];
    #pragma unroll
    for (int j = 0; j < 8; j++)
        #pragma unroll
        for (int r = 0; r < 4; r++) o[j][r] = 0.f;
    float m0 = -1e30f, m1 = -1e30f, l0 = 0.f, l1 = 0.f;

    const int nT = Skv / 64;
    int buf = 0;

    const int rowK = (q8 >> 1) * 8 + r8;
    const int colK = (q8 & 1) * 8;
    const int rowV = lane & 15;
    const int colV = (lane >> 4) * 8;

    for (int t = 0; t < nT; t++) {
        if (t + 1 < nT) loadKV(t + 1, buf ^ 1);
        cp_commit();

        float s[8][4];
        #pragma unroll
        for (int j = 0; j < 8; j++)
            #pragma unroll
            for (int r = 0; r < 4; r++) s[j][r] = 0.f;

        const uint32_t sKb = sK + (uint32_t)(buf * 64 * 72) * 2;
        #pragma unroll
        for (int ks = 0; ks < 4; ks++) {
            #pragma unroll
            for (int p = 0; p < 4; p++) {
                uint32_t b0, b1, b2, b3;
                ldsm_x4(b0, b1, b2, b3,
                        sKb + (uint32_t)((16 * p + rowK) * 72 + colK + ks * 16) * 2);
                uint32_t f0[2] = {b0, b1}, f1[2] = {b2, b3};
                mma_f16(s[2*p],   qf[ks], f0);
                mma_f16(s[2*p+1], qf[ks], f1);
            }
        }

        float rm0 = -1e30f, rm1 = -1e30f;
        #pragma unroll
        for (int j = 0; j < 8; j++) {
            rm0 = fmaxf(rm0, fmaxf(s[j][0], s[j][1]));
            rm1 = fmaxf(rm1, fmaxf(s[j][2], s[j][3]));
        }
        rm0 = fmaxf(rm0, __shfl_xor_sync(0xffffffff, rm0, 1));
        rm0 = fmaxf(rm0, __shfl_xor_sync(0xffffffff, rm0, 2));
        rm1 = fmaxf(rm1, __shfl_xor_sync(0xffffffff, rm1, 1));
        rm1 = fmaxf(rm1, __shfl_xor_sync(0xffffffff, rm1, 2));

        float mn0 = fmaxf(m0, rm0), mn1 = fmaxf(m1, rm1);
        float f0 = __expf(m0 - mn0), f1 = __expf(m1 - mn1);
        m0 = mn0; m1 = mn1;

        float sum0 = 0.f, sum1 = 0.f;
        #pragma unroll
        for (int j = 0; j < 8; j++) {
            s[j][0] = __expf(s[j][0] - mn0);
            s[j][1] = __expf(s[j][1] - mn0);
            s[j][2] = __expf(s[j][2] - mn1);
            s[j][3] = __expf(s[j][3] - mn1);
            sum0 += s[j][0] + s[j][1];
            sum1 += s[j][2] + s[j][3];
        }
        sum0 += __shfl_xor_sync(0xffffffff, sum0, 1);
        sum0 += __shfl_xor_sync(0xffffffff, sum0, 2);
        sum1 += __shfl_xor_sync(0xffffffff, sum1, 1);
        sum1 += __shfl_xor_sync(0xffffffff, sum1, 2);
        l0 = l0 * f0 + sum0;
        l1 = l1 * f1 + sum1;

        #pragma unroll
        for (int j = 0; j < 8; j++) {
            o[j][0] *= f0; o[j][1] *= f0;
            o[j][2] *= f1; o[j][3] *= f1;
        }

        const uint32_t sVb = sV + (uint32_t)(buf * 64 * 72) * 2;
        #pragma unroll
        for (int jk = 0; jk < 4; jk++) {
            uint32_t af[4];
            af[0] = pack_h2(s[2*jk][0],   s[2*jk][1]);
            af[1] = pack_h2(s[2*jk][2],   s[2*jk][3]);
            af[2] = pack_h2(s[2*jk+1][0], s[2*jk+1][1]);
            af[3] = pack_h2(s[2*jk+1][2], s[2*jk+1][3]);
            const uint32_t base = sVb + (uint32_t)((16 * jk + rowV) * 72 + colV) * 2;
            #pragma unroll
            for (int jp = 0; jp < 4; jp++) {
                uint32_t b0, b1, b2, b3;
                ldsm_x4_trans(b0, b1, b2, b3, base + (uint32_t)(16 * jp) * 2);
                uint32_t f0[2] = {b0, b1}, f1[2] = {b2, b3};
                mma_f16(o[2*jp],   af, f0);
                mma_f16(o[2*jp+1], af, f1);
            }
        }

        cp_wait<0>();
        __syncthreads();
        buf ^= 1;
    }

    float inv0 = 1.0f / l0, inv1 = 1.0f / l1;
    #pragma unroll
    for (int j = 0; j < 8; j++) {
        int col = 8 * j + 2 * c4;
        *(__half2*)(Ob + (size_t)(wid * 16 + g    ) * INNER + col) =
            __floats2half2_rn(o[j][0] * inv0, o[j][1] * inv0);
        *(__half2*)(Ob + (size_t)(wid * 16 + g + 8) * INNER + col) =
            __floats2half2_rn(o[j][2] * inv1, o[j][3] * inv1);
    }
}

// ---------------- fp32 -> fp16 conversion ----------------------------------------
__device__ __forceinline__ uint2 cvt4(float4 t) {
    __half2 lo = __floats2half2_rn(t.x, t.y);
    __half2 hi = __floats2half2_rn(t.z, t.w);
    uint2 o;
    o.x = *(uint32_t*)&lo;
    o.y = *(uint32_t*)&hi;
    return o;
}
__global__ void f32_to_f16_kernel(const float4* __restrict__ in, uint2* __restrict__ out, int n4)
{
    int i = blockIdx.x * blockDim.x + threadIdx.x;
    if (i < n4) out[i] = cvt4(in[i]);
}
__global__ void f32_to_f16_ileave(const float4* __restrict__ gsrc, const float4* __restrict__ usrc,
                                  uint2* __restrict__ out, int n4, int cols4)
{
    int i = blockIdx.x * blockDim.x + threadIdx.x;
    if (i < n4) {
        int r = i / cols4, c = i - r * cols4;
        out[(size_t)(2 * r) * cols4 + c]     = cvt4(gsrc[i]);
        out[(size_t)(2 * r + 1) * cols4 + c] = cvt4(usrc[i]);
    }
}

// ---------------- modulation (fp32) ----------------------------------------------
__global__ void mod_kernel(const float* __restrict__ cond,
                           const float* __restrict__ mw0, const float* __restrict__ mb0,
                           const float* __restrict__ mw1, const float* __restrict__ mb1,
                           const float* __restrict__ mw2, const float* __restrict__ mb2,
                           float* __restrict__ mods)
{
    __shared__ float cs[Bb * Dm];
    for (int i = threadIdx.x; i < Bb * Dm; i += blockDim.x) cs[i] = cond[i];
    __syncthreads();

    int warp = threadIdx.x >> 5, lane = threadIdx.x & 31;
    int j = blockIdx.x * 8 + warp;
    int norm = j / (3*Dm), jj = j - norm * (3*Dm);
    const float* mw = (norm == 0) ? mw0 : (norm == 1) ? mw1 : mw2;
    const float* mb = (norm == 0) ? mb0 : (norm == 1) ? mb1 : mb2;

    float acc[Bb];
    #pragma unroll
    for (int b = 0; b < Bb; b++) acc[b] = 0.f;
    const float* wrow = mw + (size_t)jj * Dm;
    for (int d = lane; d < Dm; d += 32) {
        float w = wrow[d];
        #pragma unroll
        for (int b = 0; b < Bb; b++) acc[b] = fmaf(w, cs[b*Dm + d], acc[b]);
    }
    #pragma unroll
    for (int b = 0; b < Bb; b++)
        #pragma unroll
        for (int off = 16; off > 0; off >>= 1)
            acc[b] += __shfl_xor_sync(0xffffffff, acc[b], off);
    if (lane < Bb)
        mods[(size_t)norm * Bb * 3*Dm + lane * 3*Dm + jj] = acc[lane] + mb[jj];
}

// ---------------- adaRMS norm (fp16 output) --------------------------------------
__global__ void rmsnorm_kernel(const float* __restrict__ x, const float* __restrict__ w,
                               const float* __restrict__ mod_base,
                               __half* __restrict__ out)
{
    int row = blockIdx.x;
    int b   = row / Nn;
    const float* xr = x + (size_t)row * Dm;
    const float* ms = mod_base + b * 3*Dm;

    float ss = 0.f;
    for (int i = threadIdx.x; i < Dm; i += blockDim.x) { float t = xr[i]; ss = fmaf(t,t,ss); }
    #pragma unroll
    for (int off = 16; off > 0; off >>= 1) ss += __shfl_xor_sync(0xffffffff, ss, off);
    __shared__ float red[8];
    if ((threadIdx.x & 31) == 0) red[threadIdx.x >> 5] = ss;
    __syncthreads();
    if (threadIdx.x < 8) {
        float v = red[threadIdx.x];
        #pragma unroll
        for (int off = 4; off > 0; off >>= 1) v += __shfl_xor_sync(0xff, v, off);
        if (threadIdx.x == 0) red[0] = v;
    }
    __syncthreads();
    float rn = rsqrtf(red[0] * (1.0f/Dm) + EPSf);

    __half* orow = out + (size_t)row * Dm;
    for (int i = threadIdx.x; i < Dm/2; i += blockDim.x) {
        int i2 = 2 * i;
        float a = xr[i2]   * rn * w[i2]   * (1.0f + ms[i2])   + ms[Dm + i2];
        float c = xr[i2+1] * rn * w[i2+1] * (1.0f + ms[i2+1]) + ms[Dm + i2+1];
        *(__half2*)(orow + i2) = __floats2half2_rn(a, c);
    }
}

// ---------------- host orchestration -------------------------------------------
static void* symv(const void* s) { void* p = nullptr; cudaGetSymbolAddress(&p, s); return p; }

template<int EPI,int OH>
static void gemm_h(cudaStream_t st, const __half* A, const __half* W, void* C,
                   int M, int N, int K,
                   const float* resid, const float* gate, int gate_ld, int rpb)
{
    size_t sm = (size_t)3 * (128 + 128) * 72 * sizeof(__half);   // 110592
    cudaFuncSetAttribute(gemm_f16<EPI,OH>,
                         cudaFuncAttributeMaxDynamicSharedMemorySize, (int)sm);
    gemm_f16<EPI,OH><<<dim3(N/128, M/128), 128, sm, st>>>(
        A, W, C, K, K, K, N, resid, gate, gate_ld, rpb);
}

static void cvt_to(cudaStream_t st, __half* dst, const float* src, int n)
{
    f32_to_f16_kernel<<<(n/4 + 255)/256, 256, 0, st>>>((const float4*)src, (uint2*)dst, n/4);
}

static void launch_flash(const __half* q, const __half* k, const __half* v, __half* o,
                         int Skv, int ldq, int ldkv)
{
    size_t sm = (size_t)(128*72 + 2*64*72 + 2*64*72) * sizeof(__half);  // 55296
    cudaFuncSetAttribute(flash_kernel, cudaFuncAttributeMaxDynamicSharedMemorySize, (int)sm);
    flash_kernel<<<dim3(Nn/128, Hh, Bb), 256, sm>>>(q, k, v, o, Skv, ldq, ldkv);
}

extern "C" void kernel_launch(void* const* d_in, const int* in_sizes, int n_in,
                              void* d_out, int out_size)
{
    const float* x       = (const float*)d_in[0];
    const float* context = (const float*)d_in[1];
    const float* cond    = (const float*)d_in[2];
    const float* n1_w  = (const float*)d_in[3];
    const float* n1_mw = (const float*)d_in[4];
    const float* n1_mb = (const float*)d_in[5];
    const float* n2_w  = (const float*)d_in[6];
    const float* n2_mw = (const float*)d_in[7];
    const float* n2_mb = (const float*)d_in[8];
    const float* n3_w  = (const float*)d_in[9];
    const float* n3_mw = (const float*)d_in[10];
    const float* n3_mb = (const float*)d_in[11];
    const float* sa_q  = (const float*)d_in[12];
    const float* sa_k  = (const float*)d_in[13];
    const float* sa_v  = (const float*)d_in[14];
    const float* sa_o  = (const float*)d_in[15];
    const float* ca_q  = (const float*)d_in[16];
    const float* ca_k  = (const float*)d_in[17];
    const float* ca_v  = (const float*)d_in[18];
    const float* ca_o  = (const float*)d_in[19];
    const float* ff_gate = (const float*)d_in[20];
    const float* ff_up   = (const float*)d_in[21];
    const float* ff_down = (const float*)d_in[22];
    float* out = (float*)d_out;

    float*  mods   = (float*)symv(d_mods);
    __half* normed = (__half*)symv(d_normed);
    __half* qkv    = (__half*)symv(d_qkv);
    __half* kv     = (__half*)symv(d_kv);
    __half* ao     = (__half*)symv(d_attno);
    float*  x1     = (float*)symv(d_x1);
    float*  x2     = (float*)symv(d_x2);
    __half* hb     = (__half*)symv(d_hbuf);
    __half* ctx    = (__half*)symv(d_ctx);
    __half* wr     = (__half*)symv(d_wrnd);

    const int MQ = Bb * Nn;

    static cudaStream_t s2 = nullptr, s3 = nullptr;
    static cudaEvent_t evFork = nullptr, evKV = nullptr, evW3 = nullptr;
    if (s2 == nullptr) {
        int loPri, hiPri;
        cudaDeviceGetStreamPriorityRange(&loPri, &hiPri);
        cudaStreamCreateWithPriority(&s2, cudaStreamNonBlocking, hiPri);  // KV branch wins SMs
        cudaStreamCreateWithFlags(&s3, cudaStreamNonBlocking);
        cudaEventCreateWithFlags(&evFork, cudaEventDisableTiming);
        cudaEventCreateWithFlags(&evKV, cudaEventDisableTiming);
        cudaEventCreateWithFlags(&evW3, cudaEventDisableTiming);
    }

    // ---- fork ----
    cudaEventRecord(evFork, 0);
    cudaStreamWaitEvent(s2, evFork, 0);
    cudaStreamWaitEvent(s3, evFork, 0);

    // s2: CA K/V branch (converts + the big KV GEMM)
    cvt_to(s2, wr + W_CAK,             ca_k, INNER*Cm);
    cvt_to(s2, wr + W_CAK + 2048*1024, ca_v, INNER*Cm);
    cvt_to(s2, ctx, context, Bb*Ss*Cm);
    gemm_h<0,1>(s2, ctx, wr + W_CAK, kv, Bb*Ss, 2*INNER, Cm, nullptr, nullptr, 0, 1);
    cudaEventRecord(evKV, s2);

    // s3: non-critical weight converts
    cvt_to(s3, wr + W_SAO, sa_o, Dm*INNER);
    cvt_to(s3, wr + W_CAQ, ca_q, INNER*Dm);
    cvt_to(s3, wr + W_CAO, ca_o, Dm*INNER);
    f32_to_f16_ileave<<<(MLPm*Dm/4 + 255)/256, 256, 0, s3>>>(
        (const float4*)ff_gate, (const float4*)ff_up,
        (uint2*)(wr + W_FFGU), MLPm*Dm/4, Dm/4);
    cvt_to(s3, wr + W_FFD, ff_down, Dm*MLPm);
    cudaEventRecord(evW3, s3);

    // main stream: minimal prefix
    cvt_to(0, wr + W_SAQ,             sa_q, INNER*Dm);
    cvt_to(0, wr + W_SAQ + 1024*1024, sa_k, INNER*Dm);
    cvt_to(0, wr + W_SAQ + 2048*1024, sa_v, INNER*Dm);
    mod_kernel<<<(3*3*Dm)/8, 256>>>(cond, n1_mw, n1_mb, n2_mw, n2_mb, n3_mw, n3_mb, mods);

    // ===================== Self attention =====================
    rmsnorm_kernel<<<MQ, 256>>>(x, n1_w, mods + 0*Bb*3*Dm, normed);
    gemm_h<0,1>(0, normed, wr + W_SAQ, qkv, MQ, 3*INNER, Dm, nullptr, nullptr, 0, 1);
    launch_flash(qkv, qkv + INNER, qkv + 2*INNER, ao, Nn, 3*INNER, 3*INNER);
    cudaStreamWaitEvent(0, evW3, 0);
    gemm_h<1,0>(0, ao, wr + W_SAO, x1, MQ, Dm, INNER, x, mods + 0*Bb*3*Dm + 2*Dm, 3*Dm, Nn);

    // ===================== Cross attention =====================
    rmsnorm_kernel<<<MQ, 256>>>(x1, n2_w, mods + 1*Bb*3*Dm, normed);
    gemm_h<0,1>(0, normed, wr + W_CAQ, qkv, MQ, INNER, Dm, nullptr, nullptr, 0, 1);
    cudaStreamWaitEvent(0, evKV, 0);
    launch_flash(qkv, kv, kv + INNER, ao, Ss, INNER, 2*INNER);
    gemm_h<1,0>(0, ao, wr + W_CAO, x2, MQ, Dm, INNER, x1, mods + 1*Bb*3*Dm + 2*Dm, 3*Dm, Nn);

    // ===================== FFN =====================
    rmsnorm_kernel<<<MQ, 256>>>(x2, n3_w, mods + 2*Bb*3*Dm, normed);
    gemm_h<0,2>(0, normed, wr + W_FFGU, hb, MQ, 2*MLPm, Dm, nullptr, nullptr, 0, 1);
    gemm_h<1,0>(0, hb, wr + W_FFD, out, MQ, Dm, MLPm, x2, mods + 2*Bb*3*Dm + 2*Dm, 3*Dm, Nn);
}

// round 15
// speedup vs baseline: 1.0603x; 1.0448x over previous
#include <cuda_runtime.h>
#include <cuda_fp16.h>
#include <math.h>
#include <stdint.h>

// Problem dims
#define Dm    1024
#define Cm    2048
#define MLPm  4096
#define Hh    16
#define HDh   64
#define Bb    8
#define Nn    512
#define Ss    2048
#define INNER (Hh*HDh)   // 1024
#define EPSf  1e-6f

// ---------------- scratch (static device allocations) ---------------------------
__device__ __align__(16) float  d_mods  [3 * Bb * 3 * Dm];
__device__ __align__(16) __half d_normed[Bb * Nn * Dm];
__device__ __align__(16) __half d_qkv   [Bb * Nn * 3 * INNER];
__device__ __align__(16) __half d_kv    [(size_t)Bb * Ss * 2 * INNER];
__device__ __align__(16) __half d_attno [Bb * Nn * INNER];
__device__ __align__(16) float  d_x1    [Bb * Nn * Dm];
__device__ __align__(16) float  d_x2    [Bb * Nn * Dm];
__device__ __align__(16) __half d_hbuf  [Bb * Nn * MLPm];
__device__ __align__(16) __half d_ctx   [(size_t)Bb * Ss * Cm];
__device__ __align__(16) __half d_wrnd  [22 * 1024 * 1024];

// weight offsets (elements); adjacency is load-bearing for fused GEMMs:
// [SAQ|SAK|SAV] 3072x1024, [CAK|CAV] 2048x2048, FFGU interleaved 8192x1024
#define W_SAQ  (0)
#define W_SAO  (3*1024*1024)
#define W_CAQ  (4*1024*1024)
#define W_CAK  (5*1024*1024)
#define W_CAO  (9*1024*1024)
#define W_FFGU (10*1024*1024)
#define W_FFD  (18*1024*1024)

// ---------------- helpers ---------------------------------------------------------
__device__ __forceinline__ void mma_f16(float* c, const uint32_t* a, const uint32_t* b) {
    asm volatile(
        "mma.sync.aligned.m16n8k16.row.col.f32.f16.f16.f32 "
        "{%0,%1,%2,%3}, {%4,%5,%6,%7}, {%8,%9}, {%0,%1,%2,%3};\n"
        : "+f"(c[0]), "+f"(c[1]), "+f"(c[2]), "+f"(c[3])
        : "r"(a[0]), "r"(a[1]), "r"(a[2]), "r"(a[3]), "r"(b[0]), "r"(b[1]));
}

__device__ __forceinline__ void cpasync16(uint32_t saddr, const void* gptr) {
    asm volatile("cp.async.cg.shared.global [%0], [%1], 16;\n" :: "r"(saddr), "l"(gptr));
}
__device__ __forceinline__ void cp_commit() { asm volatile("cp.async.commit_group;\n"); }
template<int n> __device__ __forceinline__ void cp_wait() {
    asm volatile("cp.async.wait_group %0;\n" :: "n"(n));
}
__device__ __forceinline__ uint32_t cvta_smem(const void* p) {
    uint32_t a;
    asm("{ .reg .u64 t; cvta.to.shared.u64 t, %1; cvt.u32.u64 %0, t; }" : "=r"(a) : "l"(p));
    return a;
}
__device__ __forceinline__ void ldsm_x4(uint32_t& r0, uint32_t& r1, uint32_t& r2, uint32_t& r3,
                                        uint32_t addr) {
    asm volatile("ldmatrix.sync.aligned.m8n8.x4.shared.b16 {%0,%1,%2,%3}, [%4];"
                 : "=r"(r0), "=r"(r1), "=r"(r2), "=r"(r3) : "r"(addr));
}
__device__ __forceinline__ void ldsm_x4_trans(uint32_t& r0, uint32_t& r1, uint32_t& r2, uint32_t& r3,
                                              uint32_t addr) {
    asm volatile("ldmatrix.sync.aligned.m8n8.x4.trans.shared.b16 {%0,%1,%2,%3}, [%4];"
                 : "=r"(r0), "=r"(r1), "=r"(r2), "=r"(r3) : "r"(addr));
}
__device__ __forceinline__ uint32_t pack_h2(float a, float b) {
    __half2 h = __floats2half2_rn(a, b);
    return *(uint32_t*)&h;
}

// ---------------- fp16 NT GEMM: C(M,N) = A(M,K) @ B(N,K)^T ----------------------
// R12 structure (measured best): 128x128 CTA, 4 warps 2x2 (warp tile 64x64),
// BK=64, LDH=72, 3-stage ring, load issued AFTER compute, single barrier/tile,
// 2 CTAs/SM.
// EPI==1: add resid + gate[(row/rows_per_b)*gate_ld+col]*acc (float out)
// OH: 0 = float out, 1 = half out, 2 = silu-pair: h[row][col/2] = silu(even)*odd
template<int EPI,int OH>
__global__ void __launch_bounds__(128, 2)
gemm_f16(const __half* __restrict__ A, const __half* __restrict__ Bg, void* __restrict__ Cv,
         int K, int lda, int ldb, int ldc,
         const float* __restrict__ resid, const float* __restrict__ gate,
         int gate_ld, int rows_per_b)
{
    constexpr int BM = 128, BN = 128, BK = 64, LDH = 72, ST = 3;

    extern __shared__ __half hsm[];
    __half* As = hsm;
    __half* Bs = hsm + ST * BM * LDH;

    const int tid = threadIdx.x, wid = tid >> 5, lane = tid & 31;
    const int g = lane >> 2, c4 = lane & 3;
    const int q8 = lane >> 3, r8 = lane & 7;
    const int wm = wid & 1, wn = wid >> 1;
    const int row0 = blockIdx.y * BM, col0 = blockIdx.x * BN;

    const __half* Arow = A  + (size_t)row0 * lda;
    const __half* Brow = Bg + (size_t)col0 * ldb;

    const uint32_t sA = cvta_smem(As);
    const uint32_t sB = cvta_smem(Bs);
    const int ldRow = tid >> 3;
    const int ldCol = (tid & 7) * 8;

    const int rowA = wm * 64 + (q8 & 1) * 8 + r8;
    const int colA = (q8 >> 1) * 8;
    const int rowB = wn * 64 + (q8 >> 1) * 8 + r8;
    const int colB = (q8 & 1) * 8;

    auto load_tile = [&](int t) {
        const int st = t % ST;
        const int kt = t * BK;
        #pragma unroll
        for (int i = 0; i < 8; i++) {
            int r = i * 16 + ldRow;
            cpasync16(sA + (uint32_t)((st * BM + r) * LDH + ldCol) * 2,
                      Arow + (size_t)r * lda + kt + ldCol);
        }
        #pragma unroll
        for (int i = 0; i < 8; i++) {
            int r = i * 16 + ldRow;
            cpasync16(sB + (uint32_t)((st * BN + r) * LDH + ldCol) * 2,
                      Brow + (size_t)r * ldb + kt + ldCol);
        }
    };

    const int nT = K / BK;
    load_tile(0); cp_commit();
    load_tile(1); cp_commit();
    cp_wait<1>();
    __syncthreads();

    float acc[4][8][4];
    #pragma unroll
    for (int i = 0; i < 4; i++)
        #pragma unroll
        for (int j = 0; j < 8; j++)
            #pragma unroll
            for (int r = 0; r < 4; r++) acc[i][j][r] = 0.f;

    for (int t = 0; t < nT; t++) {
        const uint32_t aBase = sA + (uint32_t)((t % ST) * BM * LDH) * 2;
        const uint32_t bBase = sB + (uint32_t)((t % ST) * BN * LDH) * 2;

        #pragma unroll
        for (int ks = 0; ks < 4; ks++) {
            uint32_t af[4][4], bf[8][2];
            #pragma unroll
            for (int i = 0; i < 4; i++)
                ldsm_x4(af[i][0], af[i][1], af[i][2], af[i][3],
                        aBase + (uint32_t)((rowA + 16 * i) * LDH + colA + ks * 16) * 2);
            #pragma unroll
            for (int p = 0; p < 4; p++) {
                uint32_t b0, b1, b2, b3;
                ldsm_x4(b0, b1, b2, b3,
                        bBase + (uint32_t)((rowB + 16 * p) * LDH + colB + ks * 16) * 2);
                bf[2*p][0] = b0; bf[2*p][1] = b1;
                bf[2*p+1][0] = b2; bf[2*p+1][1] = b3;
            }
            #pragma unroll
            for (int i = 0; i < 4; i++)
                #pragma unroll
                for (int j = 0; j < 8; j++)
                    mma_f16(acc[i][j], af[i], bf[j]);
        }

        if (t + 2 < nT) load_tile(t + 2);
        cp_commit();
        cp_wait<1>();
        __syncthreads();
    }

    #pragma unroll
    for (int i = 0; i < 4; i++) {
        #pragma unroll
        for (int j = 0; j < 8; j++) {
            int col = col0 + wn * 64 + 8 * j + 2 * c4;
            #pragma unroll
            for (int h = 0; h < 2; h++) {
                int row = row0 + wm * 64 + 16 * i + g + 8 * h;
                float v0 = acc[i][j][2 * h + 0];
                float v1 = acc[i][j][2 * h + 1];
                if (EPI == 1) {
                    const float* rr = resid + (size_t)row * ldc + col;
                    const float* gg = gate + (size_t)(row / rows_per_b) * gate_ld + col;
                    v0 = rr[0] + gg[0] * v0;
                    v1 = rr[1] + gg[1] * v1;
                }
                if (OH == 1) {
                    *(__half2*)((__half*)Cv + (size_t)row * ldc + col) =
                        __floats2half2_rn(v0, v1);
                } else if (OH == 0) {
                    *(float2*)((float*)Cv + (size_t)row * ldc + col) = make_float2(v0, v1);
                } else {
                    float sv = (v0 / (1.0f + __expf(-v0))) * v1;
                    ((__half*)Cv)[(size_t)row * (ldc >> 1) + (col >> 1)] = __float2half_rn(sv);
                }
            }
        }
    }
}

// ---------------- fused flash attention (fp16 mma, register-resident P) ----------
__global__ void __launch_bounds__(256, 2)
flash_kernel(const __half* __restrict__ Qg, const __half* __restrict__ Kg,
             const __half* __restrict__ Vg, __half* __restrict__ Og,
             int Skv, int ldq, int ldkv)
{
    const int h = blockIdx.y, b = blockIdx.z;
    const int n0 = blockIdx.x * 128;
    const __half* Qb = Qg + (size_t)b * Nn * ldq + (size_t)n0 * ldq + h * HDh;
    const __half* Kb = Kg + (size_t)b * Skv * ldkv + h * HDh;
    const __half* Vb = Vg + (size_t)b * Skv * ldkv + h * HDh;
    __half* Ob = Og + (size_t)b * Nn * INNER + (size_t)n0 * INNER + h * HDh;

    extern __shared__ __half fsm[];
    __half* Qs = fsm;                      // [128][72]
    __half* Ks = Qs + 128 * 72;            // [2][64][72]
    __half* Vs = Ks + 2 * 64 * 72;         // [2][64][72]

    const int tid = threadIdx.x, wid = tid >> 5, lane = tid & 31;
    const int g = lane >> 2, c4 = lane & 3;
    const int q8 = lane >> 3, r8 = lane & 7;

    const uint32_t sK = cvta_smem(Ks);
    const uint32_t sV = cvta_smem(Vs);

    {
        const __half2 sc2 = __floats2half2_rn(0.125f, 0.125f);
        #pragma unroll
        for (int it = 0; it < 4; it++) {
            int idx = it * 256 + tid;
            int r = idx >> 3, c = (idx & 7) * 8;
            uint4 qv = *(const uint4*)(Qb + (size_t)r * ldq + c);
            __half2* hp = (__half2*)&qv;
            hp[0] = __hmul2(hp[0], sc2);
            hp[1] = __hmul2(hp[1], sc2);
            hp[2] = __hmul2(hp[2], sc2);
            hp[3] = __hmul2(hp[3], sc2);
            *(uint4*)(Qs + r * 72 + c) = qv;
        }
    }

    auto loadKV = [&](int t, int buf) {
        const __half* Ksrc = Kb + (size_t)(t * 64) * ldkv;
        const __half* Vsrc = Vb + (size_t)(t * 64) * ldkv;
        #pragma unroll
        for (int it = 0; it < 2; it++) {
            int idx = it * 256 + tid;
            int r = idx >> 3, c = (idx & 7) * 8;
            cpasync16(sK + (uint32_t)((buf * 64 + r) * 72 + c) * 2, Ksrc + (size_t)r * ldkv + c);
            cpasync16(sV + (uint32_t)((buf * 64 + r) * 72 + c) * 2, Vsrc + (size_t)r * ldkv + c);
        }
    };
    loadKV(0, 0);
    cp_commit();
    cp_wait<0>();
    __syncthreads();

    uint32_t qf[4][4];
    {
        const uint32_t* Qw = (const uint32_t*)(Qs + wid * 16 * 72);
        #pragma unroll
        for (int ks = 0; ks < 4; ks++) {
            qf[ks][0] = Qw[(g    ) * 36 + 8 * ks + c4];
            qf[ks][1] = Qw[(g + 8) * 36 + 8 * ks + c4];
            qf[ks][2] = Qw[(g    ) * 36 + 8 * ks + c4 + 4];
            qf[ks][3] = Qw[(g + 8) * 36 + 8 * ks + c4 + 4];
        }
    }

    float o[8][4];
    #pragma unroll
    for (int j = 0; j < 8; j++)
        #pragma unroll
        for (int r = 0; r < 4; r++) o[j][r] = 0.f;
    float m0 = -1e30f, m1 = -1e30f, l0 = 0.f, l1 = 0.f;

    const int nT = Skv / 64;
    int buf = 0;

    const int rowK = (q8 >> 1) * 8 + r8;
    const int colK = (q8 & 1) * 8;
    const int rowV = lane & 15;
    const int colV = (lane >> 4) * 8;

    for (int t = 0; t < nT; t++) {
        if (t + 1 < nT) loadKV(t + 1, buf ^ 1);
        cp_commit();

        float s[8][4];
        #pragma unroll
        for (int j = 0; j < 8; j++)
            #pragma unroll
            for (int r = 0; r < 4; r++) s[j][r] = 0.f;

        const uint32_t sKb = sK + (uint32_t)(buf * 64 * 72) * 2;
        #pragma unroll
        for (int ks = 0; ks < 4; ks++) {
            #pragma unroll
            for (int p = 0; p < 4; p++) {
                uint32_t b0, b1, b2, b3;
                ldsm_x4(b0, b1, b2, b3,
                        sKb + (uint32_t)((16 * p + rowK) * 72 + colK + ks * 16) * 2);
                uint32_t f0[2] = {b0, b1}, f1[2] = {b2, b3};
                mma_f16(s[2*p],   qf[ks], f0);
                mma_f16(s[2*p+1], qf[ks], f1);
            }
        }

        float rm0 = -1e30f, rm1 = -1e30f;
        #pragma unroll
        for (int j = 0; j < 8; j++) {
            rm0 = fmaxf(rm0, fmaxf(s[j][0], s[j][1]));
            rm1 = fmaxf(rm1, fmaxf(s[j][2], s[j][3]));
        }
        rm0 = fmaxf(rm0, __shfl_xor_sync(0xffffffff, rm0, 1));
        rm0 = fmaxf(rm0, __shfl_xor_sync(0xffffffff, rm0, 2));
        rm1 = fmaxf(rm1, __shfl_xor_sync(0xffffffff, rm1, 1));
        rm1 = fmaxf(rm1, __shfl_xor_sync(0xffffffff, rm1, 2));

        float mn0 = fmaxf(m0, rm0), mn1 = fmaxf(m1, rm1);
        float f0 = __expf(m0 - mn0), f1 = __expf(m1 - mn1);
        m0 = mn0; m1 = mn1;

        float sum0 = 0.f, sum1 = 0.f;
        #pragma unroll
        for (int j = 0; j < 8; j++) {
            s[j][0] = __expf(s[j][0] - mn0);
            s[j][1] = __expf(s[j][1] - mn0);
            s[j][2] = __expf(s[j][2] - mn1);
            s[j][3] = __expf(s[j][3] - mn1);
            sum0 += s[j][0] + s[j][1];
            sum1 += s[j][2] + s[j][3];
        }
        sum0 += __shfl_xor_sync(0xffffffff, sum0, 1);
        sum0 += __shfl_xor_sync(0xffffffff, sum0, 2);
        sum1 += __shfl_xor_sync(0xffffffff, sum1, 1);
        sum1 += __shfl_xor_sync(0xffffffff, sum1, 2);
        l0 = l0 * f0 + sum0;
        l1 = l1 * f1 + sum1;

        #pragma unroll
        for (int j = 0; j < 8; j++) {
            o[j][0] *= f0; o[j][1] *= f0;
            o[j][2] *= f1; o[j][3] *= f1;
        }

        const uint32_t sVb = sV + (uint32_t)(buf * 64 * 72) * 2;
        #pragma unroll
        for (int jk = 0; jk < 4; jk++) {
            uint32_t af[4];
            af[0] = pack_h2(s[2*jk][0],   s[2*jk][1]);
            af[1] = pack_h2(s[2*jk][2],   s[2*jk][3]);
            af[2] = pack_h2(s[2*jk+1][0], s[2*jk+1][1]);
            af[3] = pack_h2(s[2*jk+1][2], s[2*jk+1][3]);
            const uint32_t base = sVb + (uint32_t)((16 * jk + rowV) * 72 + colV) * 2;
            #pragma unroll
            for (int jp = 0; jp < 4; jp++) {
                uint32_t b0, b1, b2, b3;
                ldsm_x4_trans(b0, b1, b2, b3, base + (uint32_t)(16 * jp) * 2);
                uint32_t f0[2] = {b0, b1}, f1[2] = {b2, b3};
                mma_f16(o[2*jp],   af, f0);
                mma_f16(o[2*jp+1], af, f1);
            }
        }

        cp_wait<0>();
        __syncthreads();
        buf ^= 1;
    }

    float inv0 = 1.0f / l0, inv1 = 1.0f / l1;
    #pragma unroll
    for (int j = 0; j < 8; j++) {
        int col = 8 * j + 2 * c4;
        *(__half2*)(Ob + (size_t)(wid * 16 + g    ) * INNER + col) =
            __floats2half2_rn(o[j][0] * inv0, o[j][1] * inv0);
        *(__half2*)(Ob + (size_t)(wid * 16 + g + 8) * INNER + col) =
            __floats2half2_rn(o[j][2] * inv1, o[j][3] * inv1);
    }
}

// ---------------- fp32 -> fp16 conversion ----------------------------------------
__device__ __forceinline__ uint2 cvt4(float4 t) {
    __half2 lo = __floats2half2_rn(t.x, t.y);
    __half2 hi = __floats2half2_rn(t.z, t.w);
    uint2 o;
    o.x = *(uint32_t*)&lo;
    o.y = *(uint32_t*)&hi;
    return o;
}
__global__ void f32_to_f16_kernel(const float4* __restrict__ in, uint2* __restrict__ out, int n4)
{
    int i = blockIdx.x * blockDim.x + threadIdx.x;
    if (i < n4) out[i] = cvt4(in[i]);
}
__global__ void f32_to_f16_ileave(const float4* __restrict__ gsrc, const float4* __restrict__ usrc,
                                  uint2* __restrict__ out, int n4, int cols4)
{
    int i = blockIdx.x * blockDim.x + threadIdx.x;
    if (i < n4) {
        int r = i / cols4, c = i - r * cols4;
        out[(size_t)(2 * r) * cols4 + c]     = cvt4(gsrc[i]);
        out[(size_t)(2 * r + 1) * cols4 + c] = cvt4(usrc[i]);
    }
}

// ---------------- modulation (fp32) ----------------------------------------------
__global__ void mod_kernel(const float* __restrict__ cond,
                           const float* __restrict__ mw0, const float* __restrict__ mb0,
                           const float* __restrict__ mw1, const float* __restrict__ mb1,
                           const float* __restrict__ mw2, const float* __restrict__ mb2,
                           float* __restrict__ mods)
{
    __shared__ float cs[Bb * Dm];
    for (int i = threadIdx.x; i < Bb * Dm; i += blockDim.x) cs[i] = cond[i];
    __syncthreads();

    int warp = threadIdx.x >> 5, lane = threadIdx.x & 31;
    int j = blockIdx.x * 8 + warp;
    int norm = j / (3*Dm), jj = j - norm * (3*Dm);
    const float* mw = (norm == 0) ? mw0 : (norm == 1) ? mw1 : mw2;
    const float* mb = (norm == 0) ? mb0 : (norm == 1) ? mb1 : mb2;

    float acc[Bb];
    #pragma unroll
    for (int b = 0; b < Bb; b++) acc[b] = 0.f;
    const float* wrow = mw + (size_t)jj * Dm;
    for (int d = lane; d < Dm; d += 32) {
        float w = wrow[d];
        #pragma unroll
        for (int b = 0; b < Bb; b++) acc[b] = fmaf(w, cs[b*Dm + d], acc[b]);
    }
    #pragma unroll
    for (int b = 0; b < Bb; b++)
        #pragma unroll
        for (int off = 16; off > 0; off >>= 1)
            acc[b] += __shfl_xor_sync(0xffffffff, acc[b], off);
    if (lane < Bb)
        mods[(size_t)norm * Bb * 3*Dm + lane * 3*Dm + jj] = acc[lane] + mb[jj];
}

// ---------------- adaRMS norm (fp16 output) --------------------------------------
__global__ void rmsnorm_kernel(const float* __restrict__ x, const float* __restrict__ w,
                               const float* __restrict__ mod_base,
                               __half* __restrict__ out)
{
    int row = blockIdx.x;
    int b   = row / Nn;
    const float* xr = x + (size_t)row * Dm;
    const float* ms = mod_base + b * 3*Dm;

    float ss = 0.f;
    for (int i = threadIdx.x; i < Dm; i += blockDim.x) { float t = xr[i]; ss = fmaf(t,t,ss); }
    #pragma unroll
    for (int off = 16; off > 0; off >>= 1) ss += __shfl_xor_sync(0xffffffff, ss, off);
    __shared__ float red[8];
    if ((threadIdx.x & 31) == 0) red[threadIdx.x >> 5] = ss;
    __syncthreads();
    if (threadIdx.x < 8) {
        float v = red[threadIdx.x];
        #pragma unroll
        for (int off = 4; off > 0; off >>= 1) v += __shfl_xor_sync(0xff, v, off);
        if (threadIdx.x == 0) red[0] = v;
    }
    __syncthreads();
    float rn = rsqrtf(red[0] * (1.0f/Dm) + EPSf);

    __half* orow = out + (size_t)row * Dm;
    for (int i = threadIdx.x; i < Dm/2; i += blockDim.x) {
        int i2 = 2 * i;
        float a = xr[i2]   * rn * w[i2]   * (1.0f + ms[i2])   + ms[Dm + i2];
        float c = xr[i2+1] * rn * w[i2+1] * (1.0f + ms[i2+1]) + ms[Dm + i2+1];
        *(__half2*)(orow + i2) = __floats2half2_rn(a, c);
    }
}

// ---------------- host orchestration -------------------------------------------
static void* symv(const void* s) { void* p = nullptr; cudaGetSymbolAddress(&p, s); return p; }

template<int EPI,int OH>
static void gemm_h(cudaStream_t st, const __half* A, const __half* W, void* C,
                   int M, int N, int K,
                   const float* resid, const float* gate, int gate_ld, int rpb)
{
    size_t sm = (size_t)3 * (128 + 128) * 72 * sizeof(__half);   // 110592
    cudaFuncSetAttribute(gemm_f16<EPI,OH>,
                         cudaFuncAttributeMaxDynamicSharedMemorySize, (int)sm);
    gemm_f16<EPI,OH><<<dim3(N/128, M/128), 128, sm, st>>>(
        A, W, C, K, K, K, N, resid, gate, gate_ld, rpb);
}

static void cvt_to(cudaStream_t st, __half* dst, const float* src, int n)
{
    f32_to_f16_kernel<<<(n/4 + 255)/256, 256, 0, st>>>((const float4*)src, (uint2*)dst, n/4);
}

static void launch_flash(const __half* q, const __half* k, const __half* v, __half* o,
                         int Skv, int ldq, int ldkv)
{
    size_t sm = (size_t)(128*72 + 2*64*72 + 2*64*72) * sizeof(__half);  // 55296
    cudaFuncSetAttribute(flash_kernel, cudaFuncAttributeMaxDynamicSharedMemorySize, (int)sm);
    flash_kernel<<<dim3(Nn/128, Hh, Bb), 256, sm>>>(q, k, v, o, Skv, ldq, ldkv);
}

extern "C" void kernel_launch(void* const* d_in, const int* in_sizes, int n_in,
                              void* d_out, int out_size)
{
    const float* x       = (const float*)d_in[0];
    const float* context = (const float*)d_in[1];
    const float* cond    = (const float*)d_in[2];
    const float* n1_w  = (const float*)d_in[3];
    const float* n1_mw = (const float*)d_in[4];
    const float* n1_mb = (const float*)d_in[5];
    const float* n2_w  = (const float*)d_in[6];
    const float* n2_mw = (const float*)d_in[7];
    const float* n2_mb = (const float*)d_in[8];
    const float* n3_w  = (const float*)d_in[9];
    const float* n3_mw = (const float*)d_in[10];
    const float* n3_mb = (const float*)d_in[11];
    const float* sa_q  = (const float*)d_in[12];
    const float* sa_k  = (const float*)d_in[13];
    const float* sa_v  = (const float*)d_in[14];
    const float* sa_o  = (const float*)d_in[15];
    const float* ca_q  = (const float*)d_in[16];
    const float* ca_k  = (const float*)d_in[17];
    const float* ca_v  = (const float*)d_in[18];
    const float* ca_o  = (const float*)d_in[19];
    const float* ff_gate = (const float*)d_in[20];
    const float* ff_up   = (const float*)d_in[21];
    const float* ff_down = (const float*)d_in[22];
    float* out = (float*)d_out;

    float*  mods   = (float*)symv(d_mods);
    __half* normed = (__half*)symv(d_normed);
    __half* qkv    = (__half*)symv(d_qkv);
    __half* kv     = (__half*)symv(d_kv);
    __half* ao     = (__half*)symv(d_attno);
    float*  x1     = (float*)symv(d_x1);
    float*  x2     = (float*)symv(d_x2);
    __half* hb     = (__half*)symv(d_hbuf);
    __half* ctx    = (__half*)symv(d_ctx);
    __half* wr     = (__half*)symv(d_wrnd);

    const int MQ = Bb * Nn;

    static cudaStream_t s2 = nullptr, s3 = nullptr;
    static cudaEvent_t evFork = nullptr, evKV = nullptr, evW0 = nullptr, evW3 = nullptr;
    if (s2 == nullptr) {
        int loPri, hiPri;
        cudaDeviceGetStreamPriorityRange(&loPri, &hiPri);
        cudaStreamCreateWithPriority(&s2, cudaStreamNonBlocking, hiPri);  // KV branch wins SMs
        cudaStreamCreateWithFlags(&s3, cudaStreamNonBlocking);
        cudaEventCreateWithFlags(&evFork, cudaEventDisableTiming);
        cudaEventCreateWithFlags(&evKV, cudaEventDisableTiming);
        cudaEventCreateWithFlags(&evW0, cudaEventDisableTiming);
        cudaEventCreateWithFlags(&evW3, cudaEventDisableTiming);
    }

    // ---- fork ----
    cudaEventRecord(evFork, 0);
    cudaStreamWaitEvent(s2, evFork, 0);
    cudaStreamWaitEvent(s3, evFork, 0);

    // s2: CA K/V branch (converts + the big KV GEMM)
    cvt_to(s2, wr + W_CAK,             ca_k, INNER*Cm);
    cvt_to(s2, wr + W_CAK + 2048*1024, ca_v, INNER*Cm);
    cvt_to(s2, ctx, context, Bb*Ss*Cm);
    gemm_h<0,1>(s2, ctx, wr + W_CAK, kv, Bb*Ss, 2*INNER, Cm, nullptr, nullptr, 0, 1);
    cudaEventRecord(evKV, s2);

    // s3: SA QKV converts FIRST (overlap with mod/rmsnorm on main), then the rest
    cvt_to(s3, wr + W_SAQ,             sa_q, INNER*Dm);
    cvt_to(s3, wr + W_SAQ + 1024*1024, sa_k, INNER*Dm);
    cvt_to(s3, wr + W_SAQ + 2048*1024, sa_v, INNER*Dm);
    cudaEventRecord(evW0, s3);
    cvt_to(s3, wr + W_SAO, sa_o, Dm*INNER);
    cvt_to(s3, wr + W_CAQ, ca_q, INNER*Dm);
    cvt_to(s3, wr + W_CAO, ca_o, Dm*INNER);
    f32_to_f16_ileave<<<(MLPm*Dm/4 + 255)/256, 256, 0, s3>>>(
        (const float4*)ff_gate, (const float4*)ff_up,
        (uint2*)(wr + W_FFGU), MLPm*Dm/4, Dm/4);
    cvt_to(s3, wr + W_FFD, ff_down, Dm*MLPm);
    cudaEventRecord(evW3, s3);

    // main stream: mod + rmsnorm run concurrently with s3's QKV converts
    mod_kernel<<<(3*3*Dm)/8, 256>>>(cond, n1_mw, n1_mb, n2_mw, n2_mb, n3_mw, n3_mb, mods);

    // ===================== Self attention =====================
    rmsnorm_kernel<<<MQ, 256>>>(x, n1_w, mods + 0*Bb*3*Dm, normed);
    cudaStreamWaitEvent(0, evW0, 0);     // join: SA QKV weights converted
    gemm_h<0,1>(0, normed, wr + W_SAQ, qkv, MQ, 3*INNER, Dm, nullptr, nullptr, 0, 1);
    launch_flash(qkv, qkv + INNER, qkv + 2*INNER, ao, Nn, 3*INNER, 3*INNER);
    cudaStreamWaitEvent(0, evW3, 0);     // join: remaining weight converts
    gemm_h<1,0>(0, ao, wr + W_SAO, x1, MQ, Dm, INNER, x, mods + 0*Bb*3*Dm + 2*Dm, 3*Dm, Nn);

    // ===================== Cross attention =====================
    rmsnorm_kernel<<<MQ, 256>>>(x1, n2_w, mods + 1*Bb*3*Dm, normed);
    gemm_h<0,1>(0, normed, wr + W_CAQ, qkv, MQ, INNER, Dm, nullptr, nullptr, 0, 1);
    cudaStreamWaitEvent(0, evKV, 0);     // join: kv ready
    launch_flash(qkv, kv, kv + INNER, ao, Ss, INNER, 2*INNER);
    gemm_h<1,0>(0, ao, wr + W_CAO, x2, MQ, Dm, INNER, x1, mods + 1*Bb*3*Dm + 2*Dm, 3*Dm, Nn);

    // ===================== FFN =====================
    rmsnorm_kernel<<<MQ, 256>>>(x2, n3_w, mods + 2*Bb*3*Dm, normed);
    gemm_h<0,2>(0, normed, wr + W_FFGU, hb, MQ, 2*MLPm, Dm, nullptr, nullptr, 0, 1);
    gemm_h<1,0>(0, hb, wr + W_FFD, out, MQ, Dm, MLPm, x2, mods + 2*Bb*3*Dm + 2*Dm, 3*Dm, Nn);
}